// round 11
// baseline (speedup 1.0000x reference)
#include <cuda_runtime.h>
#include <cuda_fp16.h>
#include <cstdint>

#define B_    8
#define HW_   32
#define C_    32
#define F_    64
#define FQ_   16
#define HO_   30
#define WO_   30
#define K_    288
#define KPADH 296   // halfs per w_sm row: 592B stride -> fl*148 mod 32 distinct per 8-lane phase

__device__ __forceinline__ unsigned h2u(__half2 h)
{
    unsigned u; memcpy(&u, &h, 4); return u;
}
__device__ __forceinline__ __half2 f_as_h2(float f)
{
    __half2 h; unsigned u = __float_as_uint(f); memcpy(&h, &u, 4); return h;
}

#define ACCH(mx, mn, pf, wf)                                                    \
    do {                                                                        \
        __half2 s_;                                                             \
        s_ = __hadd2(f_as_h2(pf.x), f_as_h2(wf.x)); mx = __hmax2(mx, s_); mn = __hmin2(mn, s_); \
        s_ = __hadd2(f_as_h2(pf.y), f_as_h2(wf.y)); mx = __hmax2(mx, s_); mn = __hmin2(mn, s_); \
        s_ = __hadd2(f_as_h2(pf.z), f_as_h2(wf.z)); mx = __hmax2(mx, s_); mn = __hmin2(mn, s_); \
        s_ = __hadd2(f_as_h2(pf.w), f_as_h2(wf.w)); mx = __hmax2(mx, s_); mn = __hmin2(mn, s_); \
    } while (0)

__global__ __launch_bounds__(128, 7)
void tropconv_h2(const float* __restrict__ x,
                 const float* __restrict__ w,
                 const float* __restrict__ bias,
                 float* __restrict__ out)
{
    __shared__ __align__(16) __half w_sm[FQ_ * KPADH];   // [16][296]  9472B
    __shared__ __align__(16) __half x_sm[3 * HW_ * C_];  // [3][32][32] 6144B

    const int tid = threadIdx.x;
    const int fq  = blockIdx.x & 3;           // filter quarter
    const int row = blockIdx.x >> 2;          // b*30 + ho
    const int ho  = row % HO_;
    const int b   = row / HO_;

    // ---- inline w transpose+convert, k-paired: 576 steps = 144 k-pairs x 4 f4 ----
    // each step: 2x LDG.128 (4 filters at k, k+1) -> 4x STS.32 packed half2 {k, k+1}
    #pragma unroll
    for (int idx = tid; idx < 576; idx += 128) {
        int k  = (idx >> 2) * 2;
        int f4 = idx & 3;
        float4 v0 = *(const float4*)(w + (k    ) * F_ + fq * FQ_ + f4 * 4);
        float4 v1 = *(const float4*)(w + (k + 1) * F_ + fq * FQ_ + f4 * 4);
        __half* base = w_sm + (f4 * 4) * KPADH + k;     // k even -> 4B aligned
        *(unsigned*)(base + 0 * KPADH) = h2u(__floats2half2_rn(v0.x, v1.x));
        *(unsigned*)(base + 1 * KPADH) = h2u(__floats2half2_rn(v0.y, v1.y));
        *(unsigned*)(base + 2 * KPADH) = h2u(__floats2half2_rn(v0.z, v1.z));
        *(unsigned*)(base + 3 * KPADH) = h2u(__floats2half2_rn(v0.w, v1.w));
    }
    // ---- inline x convert: 3 rows fp32 -> half (768 float4, 6 per thread) ----
    {
        const float4* src = (const float4*)(x + (b * HW_ + ho) * (HW_ * C_));
        uint2* dst = (uint2*)x_sm;
        #pragma unroll
        for (int idx = tid; idx < 768; idx += 128) {
            float4 v = src[idx];
            dst[idx] = make_uint2(h2u(__floats2half2_rn(v.x, v.y)),
                                  h2u(__floats2half2_rn(v.z, v.w)));
        }
    }
    __syncthreads();

    const int fl   = tid & 15;                // local filter 0..15
    const int slot = tid >> 4;                // wo-group 0..7
    const int wo_base = slot * 4;

    const char* wrowb = (const char*)w_sm + fl * (KPADH * 2);   // 592B stride, 16B aligned
    const char* xb = (const char*)x_sm;
    const float bv = __ldg(bias + fq * FQ_ + fl);

    // clamped column byte-offsets
    int coff[6];
    #pragma unroll
    for (int u = 0; u < 6; ++u) {
        int col = wo_base + u;
        if (col > 31) col = 31;               // garbage only feeds masked stores
        coff[u] = col * 64;
    }

    const __half2 HNEG = __float2half2_rn(-65504.0f);
    const __half2 HPOS = __float2half2_rn(65504.0f);
    __half2 mx2[4], mn2[4];
    #pragma unroll
    for (int t = 0; t < 4; ++t) { mx2[t] = HNEG; mn2[t] = HPOS; }

    #pragma unroll 1
    for (int c4 = 0; c4 < 4; ++c4) {          // 4 chunks of 8 channels
        #pragma unroll
        for (int i = 0; i < 3; ++i) {
            float4 pv[6];                     // broadcast LDS.128 per 8-lane phase
            #pragma unroll
            for (int u = 0; u < 6; ++u)
                pv[u] = *(const float4*)(xb + i * 2048 + coff[u] + c4 * 16);

            #pragma unroll
            for (int j = 0; j < 3; ++j) {
                float4 wv = *(const float4*)(wrowb + (i * 3 + j) * 64 + c4 * 16);
                #pragma unroll
                for (int t = 0; t < 4; ++t)
                    ACCH(mx2[t], mn2[t], pv[j + t], wv);
            }
        }
    }

    #pragma unroll
    for (int t = 0; t < 4; ++t) {
        int wo = wo_base + t;
        if (wo < WO_) {
            float hx = fmaxf(__low2float(mx2[t]), __high2float(mx2[t]));
            float hn = fminf(__low2float(mn2[t]), __high2float(mn2[t]));
            out[(row * WO_ + wo) * F_ + fq * FQ_ + fl] = hx - hn + bv;
        }
    }
}

extern "C" void kernel_launch(void* const* d_in, const int* in_sizes, int n_in,
                              void* d_out, int out_size)
{
    const float* x    = (const float*)d_in[0];
    const float* w    = (const float*)d_in[1];
    const float* bias = (const float*)d_in[2];
    float* out        = (float*)d_out;

    tropconv_h2<<<B_ * HO_ * 4, 128>>>(x, w, bias, out);
}

// round 12
// speedup vs baseline: 1.0151x; 1.0151x over previous
#include <cuda_runtime.h>
#include <cuda_fp16.h>
#include <cstdint>

#define B_    8
#define HW_   32
#define C_    32
#define F_    64
#define FQ_   16
#define HO_   30
#define WO_   30
#define K_    288
#define KPADH 296   // halfs per w_sm row: 592B stride -> fl*148 mod 32 distinct per 16-lane phase

__device__ __forceinline__ unsigned h2u(__half2 h)
{
    unsigned u; memcpy(&u, &h, 4); return u;
}
__device__ __forceinline__ __half2 u2h(unsigned u)
{
    __half2 h; memcpy(&h, &u, 4); return h;
}
__device__ __forceinline__ __half2 f_as_h2(float f)
{
    __half2 h; unsigned u = __float_as_uint(f); memcpy(&h, &u, 4); return h;
}

#define ACCH(mx, mn, pf, wf)                                                    \
    do {                                                                        \
        __half2 s_;                                                             \
        s_ = __hadd2(f_as_h2(pf.x), f_as_h2(wf.x)); mx = __hmax2(mx, s_); mn = __hmin2(mn, s_); \
        s_ = __hadd2(f_as_h2(pf.y), f_as_h2(wf.y)); mx = __hmax2(mx, s_); mn = __hmin2(mn, s_); \
        s_ = __hadd2(f_as_h2(pf.z), f_as_h2(wf.z)); mx = __hmax2(mx, s_); mn = __hmin2(mn, s_); \
        s_ = __hadd2(f_as_h2(pf.w), f_as_h2(wf.w)); mx = __hmax2(mx, s_); mn = __hmin2(mn, s_); \
    } while (0)

__global__ __launch_bounds__(256, 5)
void tropconv_h2(const float* __restrict__ x,
                 const float* __restrict__ w,
                 const float* __restrict__ bias,
                 float* __restrict__ out)
{
    __shared__ __align__(16) __half w_sm[FQ_ * KPADH];   // [16][296]  9472B
    __shared__ __align__(16) __half x_sm[3 * HW_ * C_];  // [3][32][32] 6144B

    const int tid = threadIdx.x;              // 0..255
    const int fq  = blockIdx.x & 3;           // filter quarter
    const int row = blockIdx.x >> 2;          // b*30 + ho
    const int ho  = row % HO_;
    const int b   = row / HO_;

    // ---- inline w transpose+convert, k-paired (576 steps over 256 threads) ----
    #pragma unroll
    for (int idx = tid; idx < 576; idx += 256) {
        int k  = (idx >> 2) * 2;
        int f4 = idx & 3;
        float4 v0 = *(const float4*)(w + (k    ) * F_ + fq * FQ_ + f4 * 4);
        float4 v1 = *(const float4*)(w + (k + 1) * F_ + fq * FQ_ + f4 * 4);
        __half* base = w_sm + (f4 * 4) * KPADH + k;     // k even -> 4B aligned
        *(unsigned*)(base + 0 * KPADH) = h2u(__floats2half2_rn(v0.x, v1.x));
        *(unsigned*)(base + 1 * KPADH) = h2u(__floats2half2_rn(v0.y, v1.y));
        *(unsigned*)(base + 2 * KPADH) = h2u(__floats2half2_rn(v0.z, v1.z));
        *(unsigned*)(base + 3 * KPADH) = h2u(__floats2half2_rn(v0.w, v1.w));
    }
    // ---- inline x convert: 3 rows fp32 -> half (768 float4 over 256 threads) ----
    {
        const float4* src = (const float4*)(x + (b * HW_ + ho) * (HW_ * C_));
        uint2* dst = (uint2*)x_sm;
        #pragma unroll
        for (int idx = tid; idx < 768; idx += 256) {
            float4 v = src[idx];
            dst[idx] = make_uint2(h2u(__floats2half2_rn(v.x, v.y)),
                                  h2u(__floats2half2_rn(v.z, v.w)));
        }
    }
    __syncthreads();

    const int fl    = tid & 15;               // local filter 0..15 (lane bits 0-3)
    const int khalf = (tid >> 4) & 1;         // lane bit 4: c4 chunks {0,1} or {2,3}
    const int slot  = tid >> 5;               // warp id 0..7 -> wo group
    const int wo_base = slot * 4;

    const char* wrowb = (const char*)w_sm + fl * (KPADH * 2);   // 592B stride
    const char* xb = (const char*)x_sm;

    // clamped column byte-offsets
    int coff[6];
    #pragma unroll
    for (int u = 0; u < 6; ++u) {
        int col = wo_base + u;
        if (col > 31) col = 31;               // garbage only feeds masked stores
        coff[u] = col * 64;
    }

    const __half2 HNEG = __float2half2_rn(-65504.0f);
    const __half2 HPOS = __float2half2_rn(65504.0f);
    __half2 mx2[4], mn2[4];
    #pragma unroll
    for (int t = 0; t < 4; ++t) { mx2[t] = HNEG; mn2[t] = HPOS; }

    #pragma unroll 1
    for (int cc = 0; cc < 2; ++cc) {          // this thread's 2 chunks of 8 channels
        const int c4 = khalf * 2 + cc;
        #pragma unroll
        for (int i = 0; i < 3; ++i) {
            const char* cb = xb + i * 2048 + c4 * 16;
            // rolling 4-wide pv window with manual rotation (6 loads total)
            float4 p0 = *(const float4*)(cb + coff[0]);
            float4 p1 = *(const float4*)(cb + coff[1]);
            float4 p2 = *(const float4*)(cb + coff[2]);
            float4 p3 = *(const float4*)(cb + coff[3]);
            float4 wv;
            // j = 0: cols base+0..3
            wv = *(const float4*)(wrowb + (i * 3 + 0) * 64 + c4 * 16);
            ACCH(mx2[0], mn2[0], p0, wv);
            ACCH(mx2[1], mn2[1], p1, wv);
            ACCH(mx2[2], mn2[2], p2, wv);
            ACCH(mx2[3], mn2[3], p3, wv);
            p0 = *(const float4*)(cb + coff[4]);
            // j = 1: cols base+1..4
            wv = *(const float4*)(wrowb + (i * 3 + 1) * 64 + c4 * 16);
            ACCH(mx2[0], mn2[0], p1, wv);
            ACCH(mx2[1], mn2[1], p2, wv);
            ACCH(mx2[2], mn2[2], p3, wv);
            ACCH(mx2[3], mn2[3], p0, wv);
            p1 = *(const float4*)(cb + coff[5]);
            // j = 2: cols base+2..5
            wv = *(const float4*)(wrowb + (i * 3 + 2) * 64 + c4 * 16);
            ACCH(mx2[0], mn2[0], p2, wv);
            ACCH(mx2[1], mn2[1], p3, wv);
            ACCH(mx2[2], mn2[2], p0, wv);
            ACCH(mx2[3], mn2[3], p1, wv);
        }
    }

    // ---- combine the two k-halves across lane bit 4, then store from khalf==0 ----
    const float bv = __ldg(bias + fq * FQ_ + fl);
    #pragma unroll
    for (int t = 0; t < 4; ++t) {
        __half2 omx = u2h(__shfl_xor_sync(0xffffffffu, h2u(mx2[t]), 16));
        __half2 omn = u2h(__shfl_xor_sync(0xffffffffu, h2u(mn2[t]), 16));
        __half2 fmx = __hmax2(mx2[t], omx);
        __half2 fmn = __hmin2(mn2[t], omn);
        int wo = wo_base + t;
        if (khalf == 0 && wo < WO_) {
            float hx = fmaxf(__low2float(fmx), __high2float(fmx));
            float hn = fminf(__low2float(fmn), __high2float(fmn));
            out[(row * WO_ + wo) * F_ + fq * FQ_ + fl] = hx - hn + bv;
        }
    }
}

extern "C" void kernel_launch(void* const* d_in, const int* in_sizes, int n_in,
                              void* d_out, int out_size)
{
    const float* x    = (const float*)d_in[0];
    const float* w    = (const float*)d_in[1];
    const float* bias = (const float*)d_in[2];
    float* out        = (float*)d_out;

    tropconv_h2<<<B_ * HO_ * 4, 256>>>(x, w, bias, out);
}